// round 14
// baseline (speedup 1.0000x reference)
#include <cuda_runtime.h>
#include <cuda_fp16.h>
#include <math.h>
#include <stdint.h>

// Problem constants
#define NPTS   16384
#define NCODES 8192
#define DIM    512

// GEMM tiling: CTA 128x256, 8 warps in 2(m) x 4(n), warp tile 64x64
#define BM 128
#define BN 256
#define BKH 32              // k halves per stage
#define NKT (DIM / BKH)     // 16 k-stages
#define PAD 40              // padded halves per smem row (80B, conflict-free)
#define A_STAGE (BM * PAD * 2)          // 10240 B
#define B_STAGE (BN * PAD * 2)          // 20480 B
#define STAGE_BYTES (A_STAGE + B_STAGE) // 30720 B
#define NSTAGE 3
#define SMEM_TOTAL (NSTAGE * STAGE_BYTES)   // 92160 B dynamic

#define CAP 256             // candidate list capacity per point
#define MARGIN 0.15f        // ~10 sigma of f16-accum score noise (verified R7-R11)

// Prologue fusion block ranges
#define PREP_A_BLOCKS (NPTS * DIM / 4 / 256)    // 8192
#define PREP_B_BLOCKS (NCODES * DIM / 4 / 256)  // 4096
#define PREP_I_BLOCKS 96
#define PREP_BLOCKS (PREP_A_BLOCKS + PREP_B_BLOCKS + PREP_I_BLOCKS)

// Scratch (device globals; no allocation allowed)
__device__ float    g_cnorm[NCODES];
__device__ int      g_hist[NCODES];
__device__ float    g_loss[1];
__device__ int      g_done[1];
__device__ __half   g_Ah[(size_t)NPTS * DIM];
__device__ __half   g_Bh[(size_t)NCODES * DIM];
__device__ int      g_cnt[NPTS];
__device__ uint32_t g_cand[(size_t)NPTS * CAP];

// ---------------------------------------------------------------------------
// PTX helpers (baseline compute_103 features only: sm_80-era)
// ---------------------------------------------------------------------------
__device__ __forceinline__ uint32_t smem_to_u32(const void* p) {
    uint32_t a;
    asm("{ .reg .u64 t; cvta.to.shared.u64 t, %1; cvt.u32.u64 %0, t; }" : "=r"(a) : "l"(p));
    return a;
}
__device__ __forceinline__ void cp_async16(uint32_t dst, const void* src) {
    asm volatile("cp.async.cg.shared.global [%0], [%1], 16;" :: "r"(dst), "l"(src) : "memory");
}
__device__ __forceinline__ void ldm4(uint32_t* r, uint32_t addr) {
    asm volatile("ldmatrix.sync.aligned.m8n8.x4.shared.b16 {%0,%1,%2,%3}, [%4];"
        : "=r"(r[0]), "=r"(r[1]), "=r"(r[2]), "=r"(r[3]) : "r"(addr));
}
// fp16-accumulator HMMA: D[16x8] f16 += A[16x16] f16 * B[16x8] f16
__device__ __forceinline__ void mma16816h(uint32_t* c, const uint32_t* a, const uint32_t* b) {
    asm volatile("mma.sync.aligned.m16n8k16.row.col.f16.f16.f16.f16 "
        "{%0,%1}, {%2,%3,%4,%5}, {%6,%7}, {%0,%1};"
        : "+r"(c[0]), "+r"(c[1])
        : "r"(a[0]), "r"(a[1]), "r"(a[2]), "r"(a[3]), "r"(b[0]), "r"(b[1]));
}

// ---------------------------------------------------------------------------
// Fused prologue: A-convert | B-convert + cnorm | init (incl. done counter).
// ---------------------------------------------------------------------------
__global__ void vq_prep_kernel(const float4* __restrict__ z,
                               const float4* __restrict__ cb) {
    const int b   = blockIdx.x;
    const int tid = threadIdx.x;

    if (b < PREP_A_BLOCKS) {
        int i = b * 256 + tid;
        float4 v = z[i];
        __half2* dst = reinterpret_cast<__half2*>(g_Ah);
        dst[2 * i + 0] = __floats2half2_rn(v.x, v.y);
        dst[2 * i + 1] = __floats2half2_rn(v.z, v.w);
    } else if (b < PREP_A_BLOCKS + PREP_B_BLOCKS) {
        __shared__ float ws[8];
        int bb = b - PREP_A_BLOCKS;
        int i  = bb * 256 + tid;          // float4 index into cb; 128 f4/row
        float4 v = cb[i];
        __half2* dst = reinterpret_cast<__half2*>(g_Bh);
        dst[2 * i + 0] = __floats2half2_rn(v.x, v.y);
        dst[2 * i + 1] = __floats2half2_rn(v.z, v.w);
        float ss = v.x * v.x + v.y * v.y + v.z * v.z + v.w * v.w;
#pragma unroll
        for (int off = 16; off > 0; off >>= 1)
            ss += __shfl_xor_sync(0xFFFFFFFFu, ss, off);
        int lane = tid & 31, wid = tid >> 5;
        if (lane == 0) ws[wid] = ss;
        __syncthreads();
        int row0 = bb * 2;                 // 2 rows per block (256 f4)
        if (tid == 0)   g_cnorm[row0]     = ws[0] + ws[1] + ws[2] + ws[3];
        if (tid == 128) g_cnorm[row0 + 1] = ws[4] + ws[5] + ws[6] + ws[7];
    } else {
        int i = (b - PREP_A_BLOCKS - PREP_B_BLOCKS) * 256 + tid;
        if (i < NCODES) g_hist[i] = 0;
        if (i < NPTS)   g_cnt[i] = 0;
        if (i == 0) { g_loss[0] = 0.0f; g_done[0] = 0; }
    }
}

// ---------------------------------------------------------------------------
// Pass 1: fp16 mma.sync GEMM, f16 accumulators, warp tile 64x64, CTA tile
// 128x256, 3-stage cp.async pipeline, one __syncthreads per k-tile.
// Fused margin candidate push. (R9 champion, unchanged.)
// ---------------------------------------------------------------------------
__global__ void __launch_bounds__(256, 2)
vq_gemm_kernel() {
    extern __shared__ __align__(16) char dynsmem[];
    __shared__ float sh_rmin[BM][4];

    const int tid  = threadIdx.x;
    const int lane = tid & 31;
    const int wid  = tid >> 5;
    const int wm   = wid >> 2;       // 2 warps along m (64 rows each)
    const int wn   = wid & 3;        // 4 warps along n (64 cols each)
    const int rowBase = blockIdx.y * BM;
    const int colBase = blockIdx.x * BN;

    const uint32_t su = smem_to_u32(dynsmem);

    const int grp = lane >> 3, lr = lane & 7;
    const uint32_t a_off = ((uint32_t)((wm * 64 + lr + ((grp & 1) ? 8 : 0)) * PAD
                                       + ((grp & 2) ? 8 : 0))) * 2u;
    const uint32_t b_off = ((uint32_t)((wn * 64 + lr + ((grp >= 2) ? 8 : 0)) * PAD
                                       + ((grp & 1) ? 8 : 0))) * 2u;

    uint32_t acc[4][8][2];
#pragma unroll
    for (int mi = 0; mi < 4; mi++)
#pragma unroll
        for (int ni = 0; ni < 8; ni++) { acc[mi][ni][0] = 0u; acc[mi][ni][1] = 0u; }

#define LOAD_TILE(s, kt) do {                                                        \
    uint32_t sbase = su + (uint32_t)(s) * STAGE_BYTES;                               \
    _Pragma("unroll")                                                                \
    for (int t = 0; t < 2; t++) {                                                    \
        int ch = tid * 2 + t, r = ch >> 2, q = ch & 3;                               \
        cp_async16(sbase + (uint32_t)(r * PAD + q * 8) * 2u,                         \
                   g_Ah + (size_t)(rowBase + r) * DIM + (kt) * BKH + q * 8);         \
    }                                                                                \
    _Pragma("unroll")                                                                \
    for (int t = 0; t < 4; t++) {                                                    \
        int ch = tid * 4 + t, r = ch >> 2, q = ch & 3;                               \
        cp_async16(sbase + A_STAGE + (uint32_t)(r * PAD + q * 8) * 2u,               \
                   g_Bh + (size_t)(colBase + r) * DIM + (kt) * BKH + q * 8);         \
    }                                                                                \
    asm volatile("cp.async.commit_group;" ::: "memory");                             \
} while (0)

    LOAD_TILE(0, 0);
    LOAD_TILE(1, 1);

    for (int kt = 0; kt < NKT; kt++) {
        const int s = kt % NSTAGE;
        if (kt < NKT - 1) {
            asm volatile("cp.async.wait_group 1;" ::: "memory");
        } else {
            asm volatile("cp.async.wait_group 0;" ::: "memory");
        }
        __syncthreads();   // single barrier per k-tile: also protects buffer
                           // (kt+2)%3, whose data was consumed in iter kt-1
        if (kt + 2 < NKT) LOAD_TILE((kt + 2) % NSTAGE, kt + 2);

        const uint32_t stA = su + (uint32_t)s * STAGE_BYTES;
        const uint32_t stB = stA + A_STAGE;
#pragma unroll
        for (int kk = 0; kk < 2; kk++) {
            uint32_t af[4][4], bf[4][4];
#pragma unroll
            for (int mi = 0; mi < 4; mi++)
                ldm4(af[mi], stA + a_off + (uint32_t)(mi * 16 * PAD * 2 + kk * 32));
#pragma unroll
            for (int n2 = 0; n2 < 4; n2++)
                ldm4(bf[n2], stB + b_off + (uint32_t)(n2 * 16 * PAD * 2 + kk * 32));
#pragma unroll
            for (int mi = 0; mi < 4; mi++)
#pragma unroll
                for (int n2 = 0; n2 < 4; n2++) {
                    uint32_t b01[2] = {bf[n2][0], bf[n2][1]};
                    uint32_t b23[2] = {bf[n2][2], bf[n2][3]};
                    mma16816h(acc[mi][2 * n2 + 0], af[mi], b01);
                    mma16816h(acc[mi][2 * n2 + 1], af[mi], b23);
                }
        }
    }
    __syncthreads();

    // ---- epilogue: scores, per-row local min, margin push ----
    const int qcol = (lane & 3) * 2;
    const int g    = lane >> 2;

    float sc[4][8][4];
#pragma unroll
    for (int mi = 0; mi < 4; mi++)
#pragma unroll
        for (int ni = 0; ni < 8; ni++) {
            int n_g = colBase + wn * 64 + ni * 8 + qcol;
            float cn0 = __ldg(&g_cnorm[n_g]);
            float cn1 = __ldg(&g_cnorm[n_g + 1]);
            float2 d01 = __half22float2(*reinterpret_cast<__half2*>(&acc[mi][ni][0]));
            float2 d23 = __half22float2(*reinterpret_cast<__half2*>(&acc[mi][ni][1]));
            sc[mi][ni][0] = cn0 - 2.0f * d01.x;
            sc[mi][ni][1] = cn1 - 2.0f * d01.y;
            sc[mi][ni][2] = cn0 - 2.0f * d23.x;
            sc[mi][ni][3] = cn1 - 2.0f * d23.y;
        }

#pragma unroll
    for (int mi = 0; mi < 4; mi++)
#pragma unroll
        for (int h = 0; h < 2; h++) {
            float mv = 3.4e38f;
#pragma unroll
            for (int ni = 0; ni < 8; ni++) {
                mv = fminf(mv, sc[mi][ni][h * 2 + 0]);
                mv = fminf(mv, sc[mi][ni][h * 2 + 1]);
            }
            mv = fminf(mv, __shfl_xor_sync(0xFFFFFFFFu, mv, 1));
            mv = fminf(mv, __shfl_xor_sync(0xFFFFFFFFu, mv, 2));
            if ((lane & 3) == 0)
                sh_rmin[wm * 64 + mi * 16 + h * 8 + g][wn] = mv;
        }
    __syncthreads();

#pragma unroll
    for (int mi = 0; mi < 4; mi++)
#pragma unroll
        for (int h = 0; h < 2; h++) {
            int r = wm * 64 + mi * 16 + h * 8 + g;
            float thr = fminf(fminf(sh_rmin[r][0], sh_rmin[r][1]),
                              fminf(sh_rmin[r][2], sh_rmin[r][3])) + MARGIN;
            int grow = rowBase + r;
#pragma unroll
            for (int ni = 0; ni < 8; ni++) {
#pragma unroll
                for (int cc = 0; cc < 2; cc++) {
                    float sv = sc[mi][ni][h * 2 + cc];
                    if (sv <= thr) {
                        int col = colBase + wn * 64 + ni * 8 + qcol + cc;
                        int pos = atomicAdd(&g_cnt[grow], 1);
                        if (pos < CAP) {
                            uint32_t hs = (uint32_t)__half_as_ushort(__float2half_rn(sv));
                            g_cand[(size_t)grow * CAP + pos] = (hs << 16) | (uint32_t)col;
                        }
                    }
                }
            }
        }
}

// ---------------------------------------------------------------------------
// Pass 2: per point — min over candidate list, exact fp32 rescore of those
// within margin, pick argmin; fused gather + loss + histogram.
// Last block to finish also computes losses + perplexity (finalize fused).
// ---------------------------------------------------------------------------
__global__ void __launch_bounds__(256)
vq_select_kernel(const float* __restrict__ z,
                 const float* __restrict__ cb,
                 float* __restrict__ out_zq,
                 float* __restrict__ out_idx,
                 float* __restrict__ out_scal) {
    __shared__ float    sh_minv;
    __shared__ int      sh_ecnt;
    __shared__ int      sh_eidx[32];
    __shared__ float    sh_ev[32];
    __shared__ float    sh_sse[8];
    __shared__ int      sh_best;
    __shared__ int      sh_last;

    const int n    = blockIdx.x;
    const int tid  = threadIdx.x;
    const int lane = tid & 31;
    const int wid  = tid >> 5;

    int cnt = g_cnt[n];
    if (cnt > CAP) cnt = CAP;
    const uint32_t* cand = g_cand + (size_t)n * CAP;

    if (tid == 0) { sh_ecnt = 0; sh_best = 0; }

    if (wid == 0) {
        float mv = 3.4e38f;
        for (int i = lane; i < cnt; i += 32) {
            float v = __half2float(__ushort_as_half((unsigned short)(cand[i] >> 16)));
            mv = fminf(mv, v);
        }
#pragma unroll
        for (int off = 16; off > 0; off >>= 1)
            mv = fminf(mv, __shfl_xor_sync(0xFFFFFFFFu, mv, off));
        if (lane == 0) sh_minv = mv;
    }
    __syncthreads();

    float thr = sh_minv + MARGIN;
    if (tid < cnt) {
        uint32_t p = cand[tid];
        float v = __half2float(__ushort_as_half((unsigned short)(p >> 16)));
        if (v <= thr) {
            int pos = atomicAdd(&sh_ecnt, 1);
            if (pos < 32) sh_eidx[pos] = (int)(p & 0xFFFFu);
        }
    }
    __syncthreads();
    int ecnt = sh_ecnt;
    if (ecnt > 32) ecnt = 32;

    for (int e = wid; e < ecnt; e += 8) {
        int k = sh_eidx[e];
        const float* xr = z  + (size_t)n * DIM;
        const float* cr = cb + (size_t)k * DIM;
        float dot = 0.0f;
#pragma unroll
        for (int d = lane; d < DIM; d += 32)
            dot = fmaf(xr[d], cr[d], dot);
#pragma unroll
        for (int off = 16; off > 0; off >>= 1)
            dot += __shfl_xor_sync(0xFFFFFFFFu, dot, off);
        if (lane == 0) sh_ev[e] = __ldg(&g_cnorm[k]) - 2.0f * dot;
    }
    __syncthreads();

    if (tid == 0) {
        float bv = 3.4e38f;
        int   bi = NCODES;
        for (int e = 0; e < ecnt; e++) {
            float v = sh_ev[e];
            int   k = sh_eidx[e];
            if (v < bv || (v == bv && k < bi)) { bv = v; bi = k; }
        }
        if (ecnt > 0) sh_best = bi;
    }
    __syncthreads();

    // fused gather + loss + hist
    const int best = sh_best;
    const float2* c2 = reinterpret_cast<const float2*>(cb + (size_t)best * DIM);
    const float2* x2 = reinterpret_cast<const float2*>(z  + (size_t)n * DIM);
    float2* o2 = reinterpret_cast<float2*>(out_zq + (size_t)n * DIM);
    float2 cv = c2[tid], xv = x2[tid];
    o2[tid] = cv;
    float dx = cv.x - xv.x, dy = cv.y - xv.y;
    float ls = dx * dx + dy * dy;
#pragma unroll
    for (int off = 16; off > 0; off >>= 1)
        ls += __shfl_xor_sync(0xFFFFFFFFu, ls, off);
    if (lane == 0) sh_sse[wid] = ls;
    __syncthreads();
    if (tid == 0) {
        float t = 0.0f;
#pragma unroll
        for (int w = 0; w < 8; w++) t += sh_sse[w];
        atomicAdd(&g_loss[0], t);
        atomicAdd(&g_hist[best], 1);
        out_idx[n] = (float)best;
        // make this block's hist/loss updates visible, then count in
        __threadfence();
        sh_last = (atomicAdd(&g_done[0], 1) == (int)gridDim.x - 1);
    }
    __syncthreads();

    // ---- fused finalize: last block computes losses + perplexity ----
    if (sh_last) {
        __shared__ float warp_s[8];
        float s = 0.0f;
        for (int i = tid; i < NCODES; i += 256) {
            float p = (float)g_hist[i] * (1.0f / (float)NPTS);
            s += p * logf(p + 1e-10f);
        }
#pragma unroll
        for (int off = 16; off > 0; off >>= 1)
            s += __shfl_xor_sync(0xFFFFFFFFu, s, off);
        if (lane == 0) warp_s[wid] = s;
        __syncthreads();
        if (tid == 0) {
            float H = 0.0f;
#pragma unroll
            for (int w = 0; w < 8; w++) H += warp_s[w];
            float L = g_loss[0] * (1.0f / ((float)NPTS * (float)DIM));
            out_scal[0] = L;            // commitment_loss
            out_scal[1] = L;            // codebook_loss
            out_scal[2] = expf(-H);     // perplexity
        }
    }
}

// ---------------------------------------------------------------------------
extern "C" void kernel_launch(void* const* d_in, const int* in_sizes, int n_in,
                              void* d_out, int out_size) {
    const float* z  = (const float*)d_in[0];   // z_e      [16,32,32,512]
    const float* cb = (const float*)d_in[1];   // codebook [8192,512]
    float* out = (float*)d_out;

    float* out_zq   = out;
    float* out_idx  = out + (size_t)NPTS * DIM;
    float* out_scal = out_idx + NPTS;

    cudaFuncSetAttribute(vq_gemm_kernel,
                         cudaFuncAttributeMaxDynamicSharedMemorySize, SMEM_TOTAL);

    vq_prep_kernel<<<PREP_BLOCKS, 256>>>((const float4*)z, (const float4*)cb);
    {
        dim3 grid(NCODES / BN, NPTS / BM);
        vq_gemm_kernel<<<grid, 256, SMEM_TOTAL>>>();
    }
    vq_select_kernel<<<NPTS, 256>>>(z, cb, out_zq, out_idx, out_scal);
}

// round 16
// speedup vs baseline: 1.0211x; 1.0211x over previous
#include <cuda_runtime.h>
#include <cuda_fp16.h>
#include <math.h>
#include <stdint.h>

// Problem constants
#define NPTS   16384
#define NCODES 8192
#define DIM    512

// GEMM tiling: CTA 128x256, 8 warps in 2(m) x 4(n), warp tile 64x64
#define BM 128
#define BN 256
#define BKH 32              // k halves per stage
#define NKT (DIM / BKH)     // 16 k-stages
#define PAD 40              // padded halves per smem row (80B, conflict-free)
#define A_STAGE (BM * PAD * 2)          // 10240 B
#define B_STAGE (BN * PAD * 2)          // 20480 B
#define STAGE_BYTES (A_STAGE + B_STAGE) // 30720 B
#define NSTAGE 3
#define SMEM_TOTAL (NSTAGE * STAGE_BYTES)   // 92160 B dynamic

#define CAP 256             // candidate list capacity per point
#define MARGIN 0.15f        // ~10 sigma of f16-accum score noise (verified R7-R14)

// Prologue fusion block ranges
#define PREP_A_BLOCKS (NPTS * DIM / 4 / 256)    // 8192
#define PREP_B_BLOCKS (NCODES * DIM / 4 / 256)  // 4096
#define PREP_I_BLOCKS 96
#define PREP_BLOCKS (PREP_A_BLOCKS + PREP_B_BLOCKS + PREP_I_BLOCKS)

// Scratch (device globals; no allocation allowed)
__device__ float    g_cnorm[NCODES];
__device__ int      g_hist[NCODES];
__device__ float    g_loss[1];
__device__ __half   g_Ah[(size_t)NPTS * DIM];
__device__ __half   g_Bh[(size_t)NCODES * DIM];
__device__ int      g_cnt[NPTS];
__device__ uint32_t g_cand[(size_t)NPTS * CAP];

// ---------------------------------------------------------------------------
// PTX helpers (baseline compute_103 features only: sm_80-era)
// ---------------------------------------------------------------------------
__device__ __forceinline__ uint32_t smem_to_u32(const void* p) {
    uint32_t a;
    asm("{ .reg .u64 t; cvta.to.shared.u64 t, %1; cvt.u32.u64 %0, t; }" : "=r"(a) : "l"(p));
    return a;
}
__device__ __forceinline__ void cp_async16(uint32_t dst, const void* src) {
    asm volatile("cp.async.cg.shared.global [%0], [%1], 16;" :: "r"(dst), "l"(src) : "memory");
}
__device__ __forceinline__ void ldm4(uint32_t* r, uint32_t addr) {
    asm volatile("ldmatrix.sync.aligned.m8n8.x4.shared.b16 {%0,%1,%2,%3}, [%4];"
        : "=r"(r[0]), "=r"(r[1]), "=r"(r[2]), "=r"(r[3]) : "r"(addr));
}
// fp16-accumulator HMMA: D[16x8] f16 += A[16x16] f16 * B[16x8] f16
__device__ __forceinline__ void mma16816h(uint32_t* c, const uint32_t* a, const uint32_t* b) {
    asm volatile("mma.sync.aligned.m16n8k16.row.col.f16.f16.f16.f16 "
        "{%0,%1}, {%2,%3,%4,%5}, {%6,%7}, {%0,%1};"
        : "+r"(c[0]), "+r"(c[1])
        : "r"(a[0]), "r"(a[1]), "r"(a[2]), "r"(a[3]), "r"(b[0]), "r"(b[1]));
}

// ---------------------------------------------------------------------------
// Fused prologue: A-convert | B-convert + cnorm | init.
// ---------------------------------------------------------------------------
__global__ void vq_prep_kernel(const float4* __restrict__ z,
                               const float4* __restrict__ cb) {
    const int b   = blockIdx.x;
    const int tid = threadIdx.x;

    if (b < PREP_A_BLOCKS) {
        int i = b * 256 + tid;
        float4 v = z[i];
        __half2* dst = reinterpret_cast<__half2*>(g_Ah);
        dst[2 * i + 0] = __floats2half2_rn(v.x, v.y);
        dst[2 * i + 1] = __floats2half2_rn(v.z, v.w);
    } else if (b < PREP_A_BLOCKS + PREP_B_BLOCKS) {
        __shared__ float ws[8];
        int bb = b - PREP_A_BLOCKS;
        int i  = bb * 256 + tid;          // float4 index into cb; 128 f4/row
        float4 v = cb[i];
        __half2* dst = reinterpret_cast<__half2*>(g_Bh);
        dst[2 * i + 0] = __floats2half2_rn(v.x, v.y);
        dst[2 * i + 1] = __floats2half2_rn(v.z, v.w);
        float ss = v.x * v.x + v.y * v.y + v.z * v.z + v.w * v.w;
#pragma unroll
        for (int off = 16; off > 0; off >>= 1)
            ss += __shfl_xor_sync(0xFFFFFFFFu, ss, off);
        int lane = tid & 31, wid = tid >> 5;
        if (lane == 0) ws[wid] = ss;
        __syncthreads();
        int row0 = bb * 2;                 // 2 rows per block (256 f4)
        if (tid == 0)   g_cnorm[row0]     = ws[0] + ws[1] + ws[2] + ws[3];
        if (tid == 128) g_cnorm[row0 + 1] = ws[4] + ws[5] + ws[6] + ws[7];
    } else {
        int i = (b - PREP_A_BLOCKS - PREP_B_BLOCKS) * 256 + tid;
        if (i < NCODES) g_hist[i] = 0;
        if (i < NPTS)   g_cnt[i] = 0;
        if (i == 0)     g_loss[0] = 0.0f;
    }
}

// ---------------------------------------------------------------------------
// Pass 1: fp16 mma.sync GEMM, f16 accumulators, warp tile 64x64, CTA tile
// 128x256, 3-stage cp.async pipeline, one __syncthreads per k-tile.
// Fused margin candidate push. (Champion configuration.)
// ---------------------------------------------------------------------------
__global__ void __launch_bounds__(256, 2)
vq_gemm_kernel() {
    extern __shared__ __align__(16) char dynsmem[];
    __shared__ float sh_rmin[BM][4];

    const int tid  = threadIdx.x;
    const int lane = tid & 31;
    const int wid  = tid >> 5;
    const int wm   = wid >> 2;       // 2 warps along m (64 rows each)
    const int wn   = wid & 3;        // 4 warps along n (64 cols each)
    const int rowBase = blockIdx.y * BM;
    const int colBase = blockIdx.x * BN;

    const uint32_t su = smem_to_u32(dynsmem);

    const int grp = lane >> 3, lr = lane & 7;
    const uint32_t a_off = ((uint32_t)((wm * 64 + lr + ((grp & 1) ? 8 : 0)) * PAD
                                       + ((grp & 2) ? 8 : 0))) * 2u;
    const uint32_t b_off = ((uint32_t)((wn * 64 + lr + ((grp >= 2) ? 8 : 0)) * PAD
                                       + ((grp & 1) ? 8 : 0))) * 2u;

    uint32_t acc[4][8][2];
#pragma unroll
    for (int mi = 0; mi < 4; mi++)
#pragma unroll
        for (int ni = 0; ni < 8; ni++) { acc[mi][ni][0] = 0u; acc[mi][ni][1] = 0u; }

#define LOAD_TILE(s, kt) do {                                                        \
    uint32_t sbase = su + (uint32_t)(s) * STAGE_BYTES;                               \
    _Pragma("unroll")                                                                \
    for (int t = 0; t < 2; t++) {                                                    \
        int ch = tid * 2 + t, r = ch >> 2, q = ch & 3;                               \
        cp_async16(sbase + (uint32_t)(r * PAD + q * 8) * 2u,                         \
                   g_Ah + (size_t)(rowBase + r) * DIM + (kt) * BKH + q * 8);         \
    }                                                                                \
    _Pragma("unroll")                                                                \
    for (int t = 0; t < 4; t++) {                                                    \
        int ch = tid * 4 + t, r = ch >> 2, q = ch & 3;                               \
        cp_async16(sbase + A_STAGE + (uint32_t)(r * PAD + q * 8) * 2u,               \
                   g_Bh + (size_t)(colBase + r) * DIM + (kt) * BKH + q * 8);         \
    }                                                                                \
    asm volatile("cp.async.commit_group;" ::: "memory");                             \
} while (0)

    LOAD_TILE(0, 0);
    LOAD_TILE(1, 1);

    for (int kt = 0; kt < NKT; kt++) {
        const int s = kt % NSTAGE;
        if (kt < NKT - 1) {
            asm volatile("cp.async.wait_group 1;" ::: "memory");
        } else {
            asm volatile("cp.async.wait_group 0;" ::: "memory");
        }
        __syncthreads();   // single barrier per k-tile: also protects buffer
                           // (kt+2)%3, whose data was consumed in iter kt-1
        if (kt + 2 < NKT) LOAD_TILE((kt + 2) % NSTAGE, kt + 2);

        const uint32_t stA = su + (uint32_t)s * STAGE_BYTES;
        const uint32_t stB = stA + A_STAGE;
#pragma unroll
        for (int kk = 0; kk < 2; kk++) {
            uint32_t af[4][4], bf[4][4];
#pragma unroll
            for (int mi = 0; mi < 4; mi++)
                ldm4(af[mi], stA + a_off + (uint32_t)(mi * 16 * PAD * 2 + kk * 32));
#pragma unroll
            for (int n2 = 0; n2 < 4; n2++)
                ldm4(bf[n2], stB + b_off + (uint32_t)(n2 * 16 * PAD * 2 + kk * 32));
#pragma unroll
            for (int mi = 0; mi < 4; mi++)
#pragma unroll
                for (int n2 = 0; n2 < 4; n2++) {
                    uint32_t b01[2] = {bf[n2][0], bf[n2][1]};
                    uint32_t b23[2] = {bf[n2][2], bf[n2][3]};
                    mma16816h(acc[mi][2 * n2 + 0], af[mi], b01);
                    mma16816h(acc[mi][2 * n2 + 1], af[mi], b23);
                }
        }
    }
    __syncthreads();

    // ---- epilogue: scores, per-row local min, margin push ----
    const int qcol = (lane & 3) * 2;
    const int g    = lane >> 2;

    float sc[4][8][4];
#pragma unroll
    for (int mi = 0; mi < 4; mi++)
#pragma unroll
        for (int ni = 0; ni < 8; ni++) {
            int n_g = colBase + wn * 64 + ni * 8 + qcol;
            float cn0 = __ldg(&g_cnorm[n_g]);
            float cn1 = __ldg(&g_cnorm[n_g + 1]);
            float2 d01 = __half22float2(*reinterpret_cast<__half2*>(&acc[mi][ni][0]));
            float2 d23 = __half22float2(*reinterpret_cast<__half2*>(&acc[mi][ni][1]));
            sc[mi][ni][0] = cn0 - 2.0f * d01.x;
            sc[mi][ni][1] = cn1 - 2.0f * d01.y;
            sc[mi][ni][2] = cn0 - 2.0f * d23.x;
            sc[mi][ni][3] = cn1 - 2.0f * d23.y;
        }

#pragma unroll
    for (int mi = 0; mi < 4; mi++)
#pragma unroll
        for (int h = 0; h < 2; h++) {
            float mv = 3.4e38f;
#pragma unroll
            for (int ni = 0; ni < 8; ni++) {
                mv = fminf(mv, sc[mi][ni][h * 2 + 0]);
                mv = fminf(mv, sc[mi][ni][h * 2 + 1]);
            }
            mv = fminf(mv, __shfl_xor_sync(0xFFFFFFFFu, mv, 1));
            mv = fminf(mv, __shfl_xor_sync(0xFFFFFFFFu, mv, 2));
            if ((lane & 3) == 0)
                sh_rmin[wm * 64 + mi * 16 + h * 8 + g][wn] = mv;
        }
    __syncthreads();

#pragma unroll
    for (int mi = 0; mi < 4; mi++)
#pragma unroll
        for (int h = 0; h < 2; h++) {
            int r = wm * 64 + mi * 16 + h * 8 + g;
            float thr = fminf(fminf(sh_rmin[r][0], sh_rmin[r][1]),
                              fminf(sh_rmin[r][2], sh_rmin[r][3])) + MARGIN;
            int grow = rowBase + r;
#pragma unroll
            for (int ni = 0; ni < 8; ni++) {
#pragma unroll
                for (int cc = 0; cc < 2; cc++) {
                    float sv = sc[mi][ni][h * 2 + cc];
                    if (sv <= thr) {
                        int col = colBase + wn * 64 + ni * 8 + qcol + cc;
                        int pos = atomicAdd(&g_cnt[grow], 1);
                        if (pos < CAP) {
                            uint32_t hs = (uint32_t)__half_as_ushort(__float2half_rn(sv));
                            g_cand[(size_t)grow * CAP + pos] = (hs << 16) | (uint32_t)col;
                        }
                    }
                }
            }
        }
}

// ---------------------------------------------------------------------------
// Pass 2: per point — min over candidate list, exact fp32 rescore of those
// within margin, pick argmin; fused gather + loss + histogram. (verified)
// ---------------------------------------------------------------------------
__global__ void __launch_bounds__(256)
vq_select_kernel(const float* __restrict__ z,
                 const float* __restrict__ cb,
                 float* __restrict__ out_zq,
                 float* __restrict__ out_idx) {
    __shared__ float    sh_minv;
    __shared__ int      sh_ecnt;
    __shared__ int      sh_eidx[32];
    __shared__ float    sh_ev[32];
    __shared__ float    sh_sse[8];
    __shared__ int      sh_best;

    const int n    = blockIdx.x;
    const int tid  = threadIdx.x;
    const int lane = tid & 31;
    const int wid  = tid >> 5;

    int cnt = g_cnt[n];
    if (cnt > CAP) cnt = CAP;
    const uint32_t* cand = g_cand + (size_t)n * CAP;

    if (tid == 0) { sh_ecnt = 0; sh_best = 0; }

    if (wid == 0) {
        float mv = 3.4e38f;
        for (int i = lane; i < cnt; i += 32) {
            float v = __half2float(__ushort_as_half((unsigned short)(cand[i] >> 16)));
            mv = fminf(mv, v);
        }
#pragma unroll
        for (int off = 16; off > 0; off >>= 1)
            mv = fminf(mv, __shfl_xor_sync(0xFFFFFFFFu, mv, off));
        if (lane == 0) sh_minv = mv;
    }
    __syncthreads();

    float thr = sh_minv + MARGIN;
    if (tid < cnt) {
        uint32_t p = cand[tid];
        float v = __half2float(__ushort_as_half((unsigned short)(p >> 16)));
        if (v <= thr) {
            int pos = atomicAdd(&sh_ecnt, 1);
            if (pos < 32) sh_eidx[pos] = (int)(p & 0xFFFFu);
        }
    }
    __syncthreads();
    int ecnt = sh_ecnt;
    if (ecnt > 32) ecnt = 32;

    for (int e = wid; e < ecnt; e += 8) {
        int k = sh_eidx[e];
        const float* xr = z  + (size_t)n * DIM;
        const float* cr = cb + (size_t)k * DIM;
        float dot = 0.0f;
#pragma unroll
        for (int d = lane; d < DIM; d += 32)
            dot = fmaf(xr[d], cr[d], dot);
#pragma unroll
        for (int off = 16; off > 0; off >>= 1)
            dot += __shfl_xor_sync(0xFFFFFFFFu, dot, off);
        if (lane == 0) sh_ev[e] = __ldg(&g_cnorm[k]) - 2.0f * dot;
    }
    __syncthreads();

    if (tid == 0) {
        float bv = 3.4e38f;
        int   bi = NCODES;
        for (int e = 0; e < ecnt; e++) {
            float v = sh_ev[e];
            int   k = sh_eidx[e];
            if (v < bv || (v == bv && k < bi)) { bv = v; bi = k; }
        }
        if (ecnt > 0) sh_best = bi;
    }
    __syncthreads();

    const int best = sh_best;
    const float2* c2 = reinterpret_cast<const float2*>(cb + (size_t)best * DIM);
    const float2* x2 = reinterpret_cast<const float2*>(z  + (size_t)n * DIM);
    float2* o2 = reinterpret_cast<float2*>(out_zq + (size_t)n * DIM);
    float2 cv = c2[tid], xv = x2[tid];
    o2[tid] = cv;
    float dx = cv.x - xv.x, dy = cv.y - xv.y;
    float ls = dx * dx + dy * dy;
#pragma unroll
    for (int off = 16; off > 0; off >>= 1)
        ls += __shfl_xor_sync(0xFFFFFFFFu, ls, off);
    if (lane == 0) sh_sse[wid] = ls;
    __syncthreads();
    if (tid == 0) {
        float t = 0.0f;
#pragma unroll
        for (int w = 0; w < 8; w++) t += sh_sse[w];
        atomicAdd(&g_loss[0], t);
        atomicAdd(&g_hist[best], 1);
        out_idx[n] = (float)best;
    }
}

// ---------------------------------------------------------------------------
// finalize: losses + perplexity (verified)
// ---------------------------------------------------------------------------
__global__ void vq_finalize_kernel(float* __restrict__ out3) {
    __shared__ float warp_s[8];
    float s = 0.0f;
    for (int i = threadIdx.x; i < NCODES; i += 256) {
        float p = (float)g_hist[i] * (1.0f / (float)NPTS);
        s += p * logf(p + 1e-10f);
    }
#pragma unroll
    for (int off = 16; off > 0; off >>= 1)
        s += __shfl_xor_sync(0xFFFFFFFFu, s, off);
    int lane = threadIdx.x & 31, wid = threadIdx.x >> 5;
    if (lane == 0) warp_s[wid] = s;
    __syncthreads();
    if (threadIdx.x == 0) {
        float H = 0.0f;
#pragma unroll
        for (int w = 0; w < 8; w++) H += warp_s[w];
        float L = g_loss[0] * (1.0f / ((float)NPTS * (float)DIM));
        out3[0] = L;            // commitment_loss
        out3[1] = L;            // codebook_loss
        out3[2] = expf(-H);     // perplexity
    }
}

// ---------------------------------------------------------------------------
extern "C" void kernel_launch(void* const* d_in, const int* in_sizes, int n_in,
                              void* d_out, int out_size) {
    const float* z  = (const float*)d_in[0];   // z_e      [16,32,32,512]
    const float* cb = (const float*)d_in[1];   // codebook [8192,512]
    float* out = (float*)d_out;

    float* out_zq   = out;
    float* out_idx  = out + (size_t)NPTS * DIM;
    float* out_scal = out_idx + NPTS;

    cudaFuncSetAttribute(vq_gemm_kernel,
                         cudaFuncAttributeMaxDynamicSharedMemorySize, SMEM_TOTAL);

    vq_prep_kernel<<<PREP_BLOCKS, 256>>>((const float4*)z, (const float4*)cb);
    {
        dim3 grid(NCODES / BN, NPTS / BM);
        vq_gemm_kernel<<<grid, 256, SMEM_TOTAL>>>();
    }
    vq_select_kernel<<<NPTS, 256>>>(z, cb, out_zq, out_idx);
    vq_finalize_kernel<<<1, 256>>>(out_scal);
}

// round 17
// speedup vs baseline: 1.0277x; 1.0064x over previous
#include <cuda_runtime.h>
#include <cuda_fp16.h>
#include <math.h>
#include <stdint.h>

// Problem constants
#define NPTS   16384
#define NCODES 8192
#define DIM    512

// GEMM tiling: CTA 128x256, 8 warps in 2(m) x 4(n), warp tile 64x64
#define BM 128
#define BN 256
#define BKH 32              // k halves per stage
#define NKT (DIM / BKH)     // 16 k-stages
#define PAD 40              // padded halves per smem row (80B, conflict-free)
#define A_STAGE (BM * PAD * 2)          // 10240 B
#define B_STAGE (BN * PAD * 2)          // 20480 B
#define STAGE_BYTES (A_STAGE + B_STAGE) // 30720 B
#define NSTAGE 3
#define SMEM_TOTAL (NSTAGE * STAGE_BYTES)   // 92160 B dynamic

#define CAP 256             // candidate list capacity per point
#define MARGIN 0.15f        // ~10 sigma of f16-accum score noise (verified R7-R16)

// Prologue fusion block ranges
#define PREP_A_BLOCKS (NPTS * DIM / 4 / 256)    // 8192
#define PREP_B_BLOCKS (NCODES * DIM / 4 / 256)  // 4096
#define PREP_I_BLOCKS 96
#define PREP_BLOCKS (PREP_A_BLOCKS + PREP_B_BLOCKS + PREP_I_BLOCKS)

// Scratch (device globals; no allocation allowed)
__device__ float    g_cnorm[NCODES];
__device__ int      g_hist[NCODES];
__device__ float    g_loss[1];
__device__ __half   g_Ah[(size_t)NPTS * DIM];
__device__ __half   g_Bh[(size_t)NCODES * DIM];
__device__ int      g_cnt[NPTS];
__device__ uint32_t g_cand[(size_t)NPTS * CAP];

// ---------------------------------------------------------------------------
// PTX helpers (baseline compute_103 features only: sm_80-era)
// ---------------------------------------------------------------------------
__device__ __forceinline__ uint32_t smem_to_u32(const void* p) {
    uint32_t a;
    asm("{ .reg .u64 t; cvta.to.shared.u64 t, %1; cvt.u32.u64 %0, t; }" : "=r"(a) : "l"(p));
    return a;
}
__device__ __forceinline__ void cp_async16(uint32_t dst, const void* src) {
    asm volatile("cp.async.cg.shared.global [%0], [%1], 16;" :: "r"(dst), "l"(src) : "memory");
}
__device__ __forceinline__ void ldm4(uint32_t* r, uint32_t addr) {
    asm volatile("ldmatrix.sync.aligned.m8n8.x4.shared.b16 {%0,%1,%2,%3}, [%4];"
        : "=r"(r[0]), "=r"(r[1]), "=r"(r[2]), "=r"(r[3]) : "r"(addr));
}
// fp16-accumulator HMMA: D[16x8] f16 += A[16x16] f16 * B[16x8] f16
__device__ __forceinline__ void mma16816h(uint32_t* c, const uint32_t* a, const uint32_t* b) {
    asm volatile("mma.sync.aligned.m16n8k16.row.col.f16.f16.f16.f16 "
        "{%0,%1}, {%2,%3,%4,%5}, {%6,%7}, {%0,%1};"
        : "+r"(c[0]), "+r"(c[1])
        : "r"(a[0]), "r"(a[1]), "r"(a[2]), "r"(a[3]), "r"(b[0]), "r"(b[1]));
}

// ---------------------------------------------------------------------------
// Fused prologue: A-convert | B-convert + cnorm | init.
// ---------------------------------------------------------------------------
__global__ void vq_prep_kernel(const float4* __restrict__ z,
                               const float4* __restrict__ cb) {
    const int b   = blockIdx.x;
    const int tid = threadIdx.x;

    if (b < PREP_A_BLOCKS) {
        int i = b * 256 + tid;
        float4 v = z[i];
        __half2* dst = reinterpret_cast<__half2*>(g_Ah);
        dst[2 * i + 0] = __floats2half2_rn(v.x, v.y);
        dst[2 * i + 1] = __floats2half2_rn(v.z, v.w);
    } else if (b < PREP_A_BLOCKS + PREP_B_BLOCKS) {
        __shared__ float ws[8];
        int bb = b - PREP_A_BLOCKS;
        int i  = bb * 256 + tid;          // float4 index into cb; 128 f4/row
        float4 v = cb[i];
        __half2* dst = reinterpret_cast<__half2*>(g_Bh);
        dst[2 * i + 0] = __floats2half2_rn(v.x, v.y);
        dst[2 * i + 1] = __floats2half2_rn(v.z, v.w);
        float ss = v.x * v.x + v.y * v.y + v.z * v.z + v.w * v.w;
#pragma unroll
        for (int off = 16; off > 0; off >>= 1)
            ss += __shfl_xor_sync(0xFFFFFFFFu, ss, off);
        int lane = tid & 31, wid = tid >> 5;
        if (lane == 0) ws[wid] = ss;
        __syncthreads();
        int row0 = bb * 2;                 // 2 rows per block (256 f4)
        if (tid == 0)   g_cnorm[row0]     = ws[0] + ws[1] + ws[2] + ws[3];
        if (tid == 128) g_cnorm[row0 + 1] = ws[4] + ws[5] + ws[6] + ws[7];
    } else {
        int i = (b - PREP_A_BLOCKS - PREP_B_BLOCKS) * 256 + tid;
        if (i < NCODES) g_hist[i] = 0;
        if (i < NPTS)   g_cnt[i] = 0;
        if (i == 0)     g_loss[0] = 0.0f;
    }
}

// ---------------------------------------------------------------------------
// Pass 1: fp16 mma.sync GEMM, f16 accumulators, warp tile 64x64, CTA tile
// 128x256, 3-stage cp.async pipeline, one __syncthreads per k-tile.
// Fused margin candidate push. (Champion configuration, unchanged.)
// ---------------------------------------------------------------------------
__global__ void __launch_bounds__(256, 2)
vq_gemm_kernel() {
    extern __shared__ __align__(16) char dynsmem[];
    __shared__ float sh_rmin[BM][4];

    const int tid  = threadIdx.x;
    const int lane = tid & 31;
    const int wid  = tid >> 5;
    const int wm   = wid >> 2;       // 2 warps along m (64 rows each)
    const int wn   = wid & 3;        // 4 warps along n (64 cols each)
    const int rowBase = blockIdx.y * BM;
    const int colBase = blockIdx.x * BN;

    const uint32_t su = smem_to_u32(dynsmem);

    const int grp = lane >> 3, lr = lane & 7;
    const uint32_t a_off = ((uint32_t)((wm * 64 + lr + ((grp & 1) ? 8 : 0)) * PAD
                                       + ((grp & 2) ? 8 : 0))) * 2u;
    const uint32_t b_off = ((uint32_t)((wn * 64 + lr + ((grp >= 2) ? 8 : 0)) * PAD
                                       + ((grp & 1) ? 8 : 0))) * 2u;

    uint32_t acc[4][8][2];
#pragma unroll
    for (int mi = 0; mi < 4; mi++)
#pragma unroll
        for (int ni = 0; ni < 8; ni++) { acc[mi][ni][0] = 0u; acc[mi][ni][1] = 0u; }

#define LOAD_TILE(s, kt) do {                                                        \
    uint32_t sbase = su + (uint32_t)(s) * STAGE_BYTES;                               \
    _Pragma("unroll")                                                                \
    for (int t = 0; t < 2; t++) {                                                    \
        int ch = tid * 2 + t, r = ch >> 2, q = ch & 3;                               \
        cp_async16(sbase + (uint32_t)(r * PAD + q * 8) * 2u,                         \
                   g_Ah + (size_t)(rowBase + r) * DIM + (kt) * BKH + q * 8);         \
    }                                                                                \
    _Pragma("unroll")                                                                \
    for (int t = 0; t < 4; t++) {                                                    \
        int ch = tid * 4 + t, r = ch >> 2, q = ch & 3;                               \
        cp_async16(sbase + A_STAGE + (uint32_t)(r * PAD + q * 8) * 2u,               \
                   g_Bh + (size_t)(colBase + r) * DIM + (kt) * BKH + q * 8);         \
    }                                                                                \
    asm volatile("cp.async.commit_group;" ::: "memory");                             \
} while (0)

    LOAD_TILE(0, 0);
    LOAD_TILE(1, 1);

    for (int kt = 0; kt < NKT; kt++) {
        const int s = kt % NSTAGE;
        if (kt < NKT - 1) {
            asm volatile("cp.async.wait_group 1;" ::: "memory");
        } else {
            asm volatile("cp.async.wait_group 0;" ::: "memory");
        }
        __syncthreads();   // single barrier per k-tile: also protects buffer
                           // (kt+2)%3, whose data was consumed in iter kt-1
        if (kt + 2 < NKT) LOAD_TILE((kt + 2) % NSTAGE, kt + 2);

        const uint32_t stA = su + (uint32_t)s * STAGE_BYTES;
        const uint32_t stB = stA + A_STAGE;
#pragma unroll
        for (int kk = 0; kk < 2; kk++) {
            uint32_t af[4][4], bf[4][4];
#pragma unroll
            for (int mi = 0; mi < 4; mi++)
                ldm4(af[mi], stA + a_off + (uint32_t)(mi * 16 * PAD * 2 + kk * 32));
#pragma unroll
            for (int n2 = 0; n2 < 4; n2++)
                ldm4(bf[n2], stB + b_off + (uint32_t)(n2 * 16 * PAD * 2 + kk * 32));
#pragma unroll
            for (int mi = 0; mi < 4; mi++)
#pragma unroll
                for (int n2 = 0; n2 < 4; n2++) {
                    uint32_t b01[2] = {bf[n2][0], bf[n2][1]};
                    uint32_t b23[2] = {bf[n2][2], bf[n2][3]};
                    mma16816h(acc[mi][2 * n2 + 0], af[mi], b01);
                    mma16816h(acc[mi][2 * n2 + 1], af[mi], b23);
                }
        }
    }
    __syncthreads();

    // ---- epilogue: scores, per-row local min, margin push ----
    const int qcol = (lane & 3) * 2;
    const int g    = lane >> 2;

    float sc[4][8][4];
#pragma unroll
    for (int mi = 0; mi < 4; mi++)
#pragma unroll
        for (int ni = 0; ni < 8; ni++) {
            int n_g = colBase + wn * 64 + ni * 8 + qcol;
            float cn0 = __ldg(&g_cnorm[n_g]);
            float cn1 = __ldg(&g_cnorm[n_g + 1]);
            float2 d01 = __half22float2(*reinterpret_cast<__half2*>(&acc[mi][ni][0]));
            float2 d23 = __half22float2(*reinterpret_cast<__half2*>(&acc[mi][ni][1]));
            sc[mi][ni][0] = cn0 - 2.0f * d01.x;
            sc[mi][ni][1] = cn1 - 2.0f * d01.y;
            sc[mi][ni][2] = cn0 - 2.0f * d23.x;
            sc[mi][ni][3] = cn1 - 2.0f * d23.y;
        }

#pragma unroll
    for (int mi = 0; mi < 4; mi++)
#pragma unroll
        for (int h = 0; h < 2; h++) {
            float mv = 3.4e38f;
#pragma unroll
            for (int ni = 0; ni < 8; ni++) {
                mv = fminf(mv, sc[mi][ni][h * 2 + 0]);
                mv = fminf(mv, sc[mi][ni][h * 2 + 1]);
            }
            mv = fminf(mv, __shfl_xor_sync(0xFFFFFFFFu, mv, 1));
            mv = fminf(mv, __shfl_xor_sync(0xFFFFFFFFu, mv, 2));
            if ((lane & 3) == 0)
                sh_rmin[wm * 64 + mi * 16 + h * 8 + g][wn] = mv;
        }
    __syncthreads();

#pragma unroll
    for (int mi = 0; mi < 4; mi++)
#pragma unroll
        for (int h = 0; h < 2; h++) {
            int r = wm * 64 + mi * 16 + h * 8 + g;
            float thr = fminf(fminf(sh_rmin[r][0], sh_rmin[r][1]),
                              fminf(sh_rmin[r][2], sh_rmin[r][3])) + MARGIN;
            int grow = rowBase + r;
#pragma unroll
            for (int ni = 0; ni < 8; ni++) {
#pragma unroll
                for (int cc = 0; cc < 2; cc++) {
                    float sv = sc[mi][ni][h * 2 + cc];
                    if (sv <= thr) {
                        int col = colBase + wn * 64 + ni * 8 + qcol + cc;
                        int pos = atomicAdd(&g_cnt[grow], 1);
                        if (pos < CAP) {
                            uint32_t hs = (uint32_t)__half_as_ushort(__float2half_rn(sv));
                            g_cand[(size_t)grow * CAP + pos] = (hs << 16) | (uint32_t)col;
                        }
                    }
                }
            }
        }
}

// ---------------------------------------------------------------------------
// Pass 2: per point — min over candidate list, exact fp32 rescore of those
// within margin, pick argmin; fused gather + loss + histogram. (verified)
// ---------------------------------------------------------------------------
__global__ void __launch_bounds__(256)
vq_select_kernel(const float* __restrict__ z,
                 const float* __restrict__ cb,
                 float* __restrict__ out_zq,
                 float* __restrict__ out_idx) {
    __shared__ float    sh_minv;
    __shared__ int      sh_ecnt;
    __shared__ int      sh_eidx[32];
    __shared__ float    sh_ev[32];
    __shared__ float    sh_sse[8];
    __shared__ int      sh_best;

    const int n    = blockIdx.x;
    const int tid  = threadIdx.x;
    const int lane = tid & 31;
    const int wid  = tid >> 5;

    int cnt = g_cnt[n];
    if (cnt > CAP) cnt = CAP;
    const uint32_t* cand = g_cand + (size_t)n * CAP;

    if (tid == 0) { sh_ecnt = 0; sh_best = 0; }

    if (wid == 0) {
        float mv = 3.4e38f;
        for (int i = lane; i < cnt; i += 32) {
            float v = __half2float(__ushort_as_half((unsigned short)(cand[i] >> 16)));
            mv = fminf(mv, v);
        }
#pragma unroll
        for (int off = 16; off > 0; off >>= 1)
            mv = fminf(mv, __shfl_xor_sync(0xFFFFFFFFu, mv, off));
        if (lane == 0) sh_minv = mv;
    }
    __syncthreads();

    float thr = sh_minv + MARGIN;
    if (tid < cnt) {
        uint32_t p = cand[tid];
        float v = __half2float(__ushort_as_half((unsigned short)(p >> 16)));
        if (v <= thr) {
            int pos = atomicAdd(&sh_ecnt, 1);
            if (pos < 32) sh_eidx[pos] = (int)(p & 0xFFFFu);
        }
    }
    __syncthreads();
    int ecnt = sh_ecnt;
    if (ecnt > 32) ecnt = 32;

    for (int e = wid; e < ecnt; e += 8) {
        int k = sh_eidx[e];
        const float* xr = z  + (size_t)n * DIM;
        const float* cr = cb + (size_t)k * DIM;
        float dot = 0.0f;
#pragma unroll
        for (int d = lane; d < DIM; d += 32)
            dot = fmaf(xr[d], cr[d], dot);
#pragma unroll
        for (int off = 16; off > 0; off >>= 1)
            dot += __shfl_xor_sync(0xFFFFFFFFu, dot, off);
        if (lane == 0) sh_ev[e] = __ldg(&g_cnorm[k]) - 2.0f * dot;
    }
    __syncthreads();

    if (tid == 0) {
        float bv = 3.4e38f;
        int   bi = NCODES;
        for (int e = 0; e < ecnt; e++) {
            float v = sh_ev[e];
            int   k = sh_eidx[e];
            if (v < bv || (v == bv && k < bi)) { bv = v; bi = k; }
        }
        if (ecnt > 0) sh_best = bi;
    }
    __syncthreads();

    const int best = sh_best;
    const float2* c2 = reinterpret_cast<const float2*>(cb + (size_t)best * DIM);
    const float2* x2 = reinterpret_cast<const float2*>(z  + (size_t)n * DIM);
    float2* o2 = reinterpret_cast<float2*>(out_zq + (size_t)n * DIM);
    float2 cv = c2[tid], xv = x2[tid];
    o2[tid] = cv;
    float dx = cv.x - xv.x, dy = cv.y - xv.y;
    float ls = dx * dx + dy * dy;
#pragma unroll
    for (int off = 16; off > 0; off >>= 1)
        ls += __shfl_xor_sync(0xFFFFFFFFu, ls, off);
    if (lane == 0) sh_sse[wid] = ls;
    __syncthreads();
    if (tid == 0) {
        float t = 0.0f;
#pragma unroll
        for (int w = 0; w < 8; w++) t += sh_sse[w];
        atomicAdd(&g_loss[0], t);
        atomicAdd(&g_hist[best], 1);
        out_idx[n] = (float)best;
    }
}

// ---------------------------------------------------------------------------
// finalize: losses + perplexity. 1024 threads (8 logs/thread) + fast-math
// intrinsics to shrink the serial single-block tail.
// ---------------------------------------------------------------------------
__global__ void __launch_bounds__(1024)
vq_finalize_kernel(float* __restrict__ out3) {
    __shared__ float warp_s[32];
    const int tid = threadIdx.x;
    float s = 0.0f;
#pragma unroll
    for (int i = tid; i < NCODES; i += 1024) {
        float p = (float)g_hist[i] * (1.0f / (float)NPTS);
        s += p * __logf(p + 1e-10f);
    }
#pragma unroll
    for (int off = 16; off > 0; off >>= 1)
        s += __shfl_xor_sync(0xFFFFFFFFu, s, off);
    int lane = tid & 31, wid = tid >> 5;
    if (lane == 0) warp_s[wid] = s;
    __syncthreads();
    if (wid == 0) {
        float t = (lane < 32) ? warp_s[lane] : 0.0f;
#pragma unroll
        for (int off = 16; off > 0; off >>= 1)
            t += __shfl_xor_sync(0xFFFFFFFFu, t, off);
        if (lane == 0) {
            float L = g_loss[0] * (1.0f / ((float)NPTS * (float)DIM));
            out3[0] = L;             // commitment_loss
            out3[1] = L;             // codebook_loss
            out3[2] = __expf(-t);    // perplexity
        }
    }
}

// ---------------------------------------------------------------------------
extern "C" void kernel_launch(void* const* d_in, const int* in_sizes, int n_in,
                              void* d_out, int out_size) {
    const float* z  = (const float*)d_in[0];   // z_e      [16,32,32,512]
    const float* cb = (const float*)d_in[1];   // codebook [8192,512]
    float* out = (float*)d_out;

    float* out_zq   = out;
    float* out_idx  = out + (size_t)NPTS * DIM;
    float* out_scal = out_idx + NPTS;

    cudaFuncSetAttribute(vq_gemm_kernel,
                         cudaFuncAttributeMaxDynamicSharedMemorySize, SMEM_TOTAL);

    vq_prep_kernel<<<PREP_BLOCKS, 256>>>((const float4*)z, (const float4*)cb);
    {
        dim3 grid(NCODES / BN, NPTS / BM);
        vq_gemm_kernel<<<grid, 256, SMEM_TOTAL>>>();
    }
    vq_select_kernel<<<NPTS, 256>>>(z, cb, out_zq, out_idx);
    vq_finalize_kernel<<<1, 1024>>>(out_scal);
}